// round 15
// baseline (speedup 1.0000x reference)
#include <cuda_runtime.h>
#include <math.h>

#define BATCH_SAMPLES 320000
#define NFRAMES 1000
#define HOP 320
#define N2 512
#define NMELS 128
#define PREEMPH 0.97f
#define PASSES 4          // frame pairs per block (8 frames)

typedef unsigned long long u64;

// ---- global tables (rebuilt every launch; deterministic) ----
__device__ float2 g_win2[400];   // hann window pairs, index p-56
__device__ float2 g_tw[257];     // exp(-i*pi*k/512)
__device__ float  g_u[512];      // per-bin up-slope weight
__device__ int    g_seg[132];    // segment starts

__global__ void setup_kernel() {
    __shared__ int s_m[512];
    int tid = threadIdx.x;  // 256
    float* gw = reinterpret_cast<float*>(g_win2);
    for (int n = tid; n < 800; n += 256)
        gw[n] = 0.5f - 0.5f * __cosf((2.0f * (float)M_PI / 799.0f) * (float)n);
    for (int k = tid; k < 257; k += 256) {
        float s, c;
        __sincosf(-((float)M_PI / 512.0f) * (float)k, &s, &c);
        g_tw[k] = make_float2(c, s);
    }
    float mel_high = 1127.0f * logf(1.0f + 16000.0f / 700.0f);
    float invd = 129.0f / mel_high;
    for (int f = tid; f < 512; f += 256) {
        float melf = 1127.0f * logf(1.0f + (float)f * (31.25f / 700.0f));
        float md = melf * invd;
        int m = (int)floorf(md);
        g_u[f] = md - (float)m;
        s_m[f] = m;
    }
    __syncthreads();
    for (int f = tid; f < 512; f += 256) {
        int m0 = s_m[f];
        int mp = (f == 0) ? -1 : s_m[f - 1];
        for (int m = mp + 1; m <= m0; ++m) g_seg[m] = f;
        if (f == 511) for (int m = m0 + 1; m <= 131; ++m) g_seg[m] = 512;
    }
}

// ---- packed f32x2 helpers ----
__device__ __forceinline__ u64 pk(float a, float b) {
    u64 r; asm("mov.b64 %0, {%1, %2};" : "=l"(r)
               : "r"(__float_as_uint(a)), "r"(__float_as_uint(b)));
    return r;
}
__device__ __forceinline__ float2 upk(u64 v) {
    unsigned lo, hi; asm("mov.b64 {%0, %1}, %2;" : "=r"(lo), "=r"(hi) : "l"(v));
    return make_float2(__uint_as_float(lo), __uint_as_float(hi));
}
__device__ __forceinline__ u64 fadd2(u64 a, u64 b) {
    u64 r; asm("add.rn.f32x2 %0, %1, %2;" : "=l"(r) : "l"(a), "l"(b)); return r;
}
__device__ __forceinline__ u64 fsub2(u64 a, u64 b) {
    u64 r; asm("sub.rn.f32x2 %0, %1, %2;" : "=l"(r) : "l"(a), "l"(b)); return r;
}
__device__ __forceinline__ u64 fmul2(u64 a, u64 b) {
    u64 r; asm("mul.rn.f32x2 %0, %1, %2;" : "=l"(r) : "l"(a), "l"(b)); return r;
}
__device__ __forceinline__ u64 ffma2(u64 a, u64 b, u64 c) {
    u64 r; asm("fma.rn.f32x2 %0, %1, %2, %3;" : "=l"(r) : "l"(a), "l"(b), "l"(c)); return r;
}

// skewed addressing over 16B slots: conflict-free for strides 1, 8, 64 and dr_oct
__device__ __forceinline__ int PHYS(int i) { return i + (i >> 3) + (i >> 6); }
// octal digit reversal of a 9-bit index
__device__ __forceinline__ int dr_oct(int k) {
    return ((k & 7) << 6) | (k & 56) | ((k >> 6) & 7);
}

// 8-point DFT on packed pairs; no negations (add/sub folded)
__device__ __forceinline__ void dft8_2(u64* r, u64* i) {
    const u64 S22 = pk(0.70710678118654752f, 0.70710678118654752f);
    u64 br0 = fadd2(r[0], r[4]), bi0 = fadd2(i[0], i[4]);
    u64 br4 = fsub2(r[0], r[4]), bi4 = fsub2(i[0], i[4]);
    u64 t1r = fsub2(r[1], r[5]), t1i = fsub2(i[1], i[5]);
    u64 br1 = fadd2(r[1], r[5]), bi1 = fadd2(i[1], i[5]);
    u64 t2r = fsub2(r[2], r[6]), t2i = fsub2(i[2], i[6]);
    u64 br2 = fadd2(r[2], r[6]), bi2 = fadd2(i[2], i[6]);
    u64 t3r = fsub2(r[3], r[7]), t3i = fsub2(i[3], i[7]);
    u64 br3 = fadd2(r[3], r[7]), bi3 = fadd2(i[3], i[7]);
    u64 br5 = fmul2(S22, fadd2(t1r, t1i));
    u64 bi5 = fmul2(S22, fsub2(t1i, t1r));
    u64 p7r = fmul2(S22, fsub2(t3i, t3r));
    u64 p7e = fmul2(S22, fadd2(t3r, t3i));   // bi7 = -p7e
    u64 c0r = fadd2(br0, br2), c0i = fadd2(bi0, bi2);
    u64 c2r = fsub2(br0, br2), c2i = fsub2(bi0, bi2);
    u64 c1r = fadd2(br1, br3), c1i = fadd2(bi1, bi3);
    u64 d1r = fsub2(br1, br3), d1i = fsub2(bi1, bi3);
    u64 c4r = fadd2(br4, t2i), c4i = fsub2(bi4, t2r);
    u64 c6r = fsub2(br4, t2i), c6i = fadd2(bi4, t2r);
    u64 c5r = fadd2(br5, p7r), c5i = fsub2(bi5, p7e);
    u64 d3r = fsub2(br5, p7r), d3i = fadd2(bi5, p7e);
    r[0] = fadd2(c0r, c1r);  i[0] = fadd2(c0i, c1i);
    r[4] = fsub2(c0r, c1r);  i[4] = fsub2(c0i, c1i);
    r[2] = fadd2(c2r, d1i);  i[2] = fsub2(c2i, d1r);
    r[6] = fsub2(c2r, d1i);  i[6] = fadd2(c2i, d1r);
    r[1] = fadd2(c4r, c5r);  i[1] = fadd2(c4i, c5i);
    r[5] = fsub2(c4r, c5r);  i[5] = fsub2(c4i, c5i);
    r[3] = fadd2(c6r, d3i);  i[3] = fsub2(c6i, d3r);
    r[7] = fsub2(c6r, d3i);  i[7] = fadd2(c6i, d3r);
}

// twiddle via w2-stepped chains (dep depth <=4, low live regs)
__device__ __forceinline__ void twiddle8_2(u64* ar, u64* ai, u64 cw, u64 sw) {
    u64 c2 = fsub2(fmul2(cw, cw), fmul2(sw, sw));
    u64 s2 = fadd2(fmul2(cw, sw), fmul2(sw, cw));
    u64 cwr = cw, cwi = sw;     // odd cursor
    u64 evr = c2, evi = s2;     // even cursor
    #pragma unroll
    for (int k = 1; k < 8; k += 2) {
        u64 tr = fsub2(fmul2(ar[k], cwr), fmul2(ai[k], cwi));
        ai[k]  = ffma2(ar[k], cwi, fmul2(ai[k], cwr));
        ar[k]  = tr;
        if (k + 1 < 8) {
            u64 ur = fsub2(fmul2(ar[k+1], evr), fmul2(ai[k+1], evi));
            ai[k+1] = ffma2(ar[k+1], evi, fmul2(ai[k+1], evr));
            ar[k+1] = ur;
        }
        u64 nr = fsub2(fmul2(cwr, c2), fmul2(cwi, s2));
        cwi    = ffma2(cwr, s2, fmul2(cwi, c2));
        cwr    = nr;
        u64 mr = fsub2(fmul2(evr, c2), fmul2(evi, s2));
        evi    = ffma2(evr, s2, fmul2(evi, c2));
        evr    = mr;
    }
}

__device__ __forceinline__ float yval(const float* __restrict__ xb, int i) {
    return (i >= 0 && i <= BATCH_SAMPLES - 2) ? (xb[i + 1] - PREEMPH * xb[i]) : 0.0f;
}

// 64 threads; block handles PASSES frame pairs sequentially
__global__ __launch_bounds__(64, 15) void logmel_kernel(
    const float* __restrict__ x,
    float* __restrict__ out)
{
    __shared__ ulonglong2 sz[592];    // (re2, im2) FFT workspace, PHYS-skewed
    __shared__ u64        spw[513];   // packed power per bin
    __shared__ float      s_u[512];

    const int lane = threadIdx.x;     // 0..63
    const int b    = blockIdx.y;
    const float* __restrict__ xb = x + (size_t)b * BATCH_SAMPLES;

    // stage u table once (ordered by the stage-1/2 syncs before first use)
    #pragma unroll
    for (int c = 0; c < 8; ++c) s_u[lane + (c << 6)] = g_u[lane + (c << 6)];

    // pass-invariant mel segment boundaries
    const int m0 = 2 * lane;
    const int fa = __ldg(&g_seg[m0]);
    const int fb = __ldg(&g_seg[m0 + 1]);
    const int fc = __ldg(&g_seg[m0 + 2]);
    const int fd = __ldg(&g_seg[m0 + 3]);

    #pragma unroll 1
    for (int pass = 0; pass < PASSES; ++pass) {
        const int t0 = (blockIdx.x * PASSES + pass) * 2;   // frames t0, t0+1
        const int basea = t0 * HOP - 512;
        u64 ar[8], ai[8];

        // ---- load + preemph + window -> packed stage-1 registers ----
        if (t0 >= 2 && t0 + 1 <= 998) {
            #pragma unroll
            for (int m = 0; m < 8; ++m) {
                int p = lane + (m << 6);
                if (p >= 56 && p < 456) {
                    int iaa = basea + 2 * p;
                    float2 va = *reinterpret_cast<const float2*>(xb + iaa);
                    float xa2 = xb[iaa + 2];
                    float2 vb = *reinterpret_cast<const float2*>(xb + iaa + HOP);
                    float xb2 = xb[iaa + HOP + 2];
                    float2 w = __ldg(&g_win2[p - 56]);
                    ar[m] = pk(w.x * (va.y - PREEMPH * va.x),
                               w.x * (vb.y - PREEMPH * vb.x));
                    ai[m] = pk(w.y * (xa2 - PREEMPH * va.y),
                               w.y * (xb2 - PREEMPH * vb.y));
                } else { ar[m] = 0ULL; ai[m] = 0ULL; }
            }
        } else {
            #pragma unroll
            for (int m = 0; m < 8; ++m) {
                int p = lane + (m << 6);
                float a0 = 0.0f, a1 = 0.0f, b0 = 0.0f, b1 = 0.0f;
                if (p >= 56 && p < 456) {
                    float2 w = __ldg(&g_win2[p - 56]);
                    a0 = w.x * yval(xb, basea + 2 * p);
                    a1 = w.y * yval(xb, basea + 2 * p + 1);
                    b0 = w.x * yval(xb, basea + HOP + 2 * p);
                    b1 = w.y * yval(xb, basea + HOP + 2 * p + 1);
                }
                ar[m] = pk(a0, b0); ai[m] = pk(a1, b1);
            }
        }

        // ---- stage 1: span 64 ----
        dft8_2(ar, ai);
        {
            float2 w = __ldg(&g_tw[2 * lane]);
            twiddle8_2(ar, ai, pk(w.x, w.x), pk(w.y, w.y));
        }
        #pragma unroll
        for (int k = 0; k < 8; ++k)
            sz[PHYS(lane + (k << 6))] = make_ulonglong2(ar[k], ai[k]);
        __syncthreads();

        // ---- stage 2: span 8 ----
        {
            const int G = lane >> 3, p = lane & 7;
            const int b0 = (G << 6) + p;
            #pragma unroll
            for (int m = 0; m < 8; ++m) {
                ulonglong2 v = sz[PHYS(b0 + (m << 3))];
                ar[m] = v.x; ai[m] = v.y;
            }
            dft8_2(ar, ai);
            float2 w = __ldg(&g_tw[p << 4]);
            twiddle8_2(ar, ai, pk(w.x, w.x), pk(w.y, w.y));
            #pragma unroll
            for (int k = 0; k < 8; ++k)
                sz[PHYS(b0 + (k << 3))] = make_ulonglong2(ar[k], ai[k]);
        }
        __syncthreads();

        // ---- stage 3: span 1; IN PLACE on thread-owned slots ----
        {
            const int b0 = lane << 3;
            #pragma unroll
            for (int m = 0; m < 8; ++m) {
                ulonglong2 v = sz[PHYS(b0 + m)];
                ar[m] = v.x; ai[m] = v.y;
            }
            dft8_2(ar, ai);
            #pragma unroll
            for (int k = 0; k < 8; ++k)
                sz[PHYS(b0 + k)] = make_ulonglong2(ar[k], ai[k]);
        }
        __syncthreads();

        // ---- real-FFT split + power; gather via dr_oct ----
        const u64 HALF = pk(0.5f, 0.5f);
        #pragma unroll
        for (int kq = 0; kq < 4; ++kq) {
            int k  = lane + (kq << 6);            // 0..255
            int k2 = (N2 - k) & (N2 - 1);
            ulonglong2 z = sz[PHYS(dr_oct(k))];
            ulonglong2 u = sz[PHYS(dr_oct(k2))];
            u64 xer  = fmul2(HALF, fadd2(z.x, u.x));
            u64 xei  = fmul2(HALF, fsub2(z.y, u.y));
            u64 xodr = fmul2(HALF, fadd2(z.y, u.y));
            u64 xodi = fmul2(HALF, fsub2(u.x, z.x));
            float2 w = __ldg(&g_tw[k]);
            u64 WC = pk(w.x, w.x), WS = pk(w.y, w.y);
            u64 tr = fsub2(fmul2(WC, xodr), fmul2(WS, xodi));
            u64 ti = ffma2(WC, xodi, fmul2(WS, xodr));
            u64 xr = fadd2(xer, tr), xi = fadd2(xei, ti);
            u64 yr = fsub2(xer, tr), yi = fsub2(xei, ti);
            spw[k]      = ffma2(xr, xr, fmul2(xi, xi));
            spw[N2 - k] = ffma2(yr, yr, fmul2(yi, yi));
        }
        if (lane == 0) {
            ulonglong2 z = sz[PHYS(dr_oct(256))];
            spw[256] = ffma2(z.x, z.x, fmul2(z.y, z.y));
        }
        __syncthreads();

        // ---- mel: thread owns mels (2*lane, 2*lane+1); each bin read once ----
        {
            u64 P0 = 0ULL, U0 = 0ULL, P1 = 0ULL, U1 = 0ULL;
            for (int f = fa; f < fb; ++f) {
                u64 p = spw[f]; float uf = s_u[f];
                P0 = fadd2(P0, p); U0 = ffma2(pk(uf, uf), p, U0);
            }
            for (int f = fb; f < fc; ++f) {
                u64 p = spw[f]; float uf = s_u[f];
                P1 = fadd2(P1, p); U1 = ffma2(pk(uf, uf), p, U1);
            }
            u64 D0 = fsub2(P0, U0);
            u64 D2 = __shfl_down_sync(0xffffffffu, D0, 1);
            if ((lane & 31) == 31) {                      // warp boundary: recompute
                u64 P2 = 0ULL, U2 = 0ULL;
                for (int f = fc; f < fd; ++f) {
                    u64 p = spw[f]; float uf = s_u[f];
                    P2 = fadd2(P2, p); U2 = ffma2(pk(uf, uf), p, U2);
                }
                D2 = fsub2(P2, U2);
            }
            u64 mel0 = fadd2(U0, fsub2(P1, U1));
            u64 mel1 = fadd2(U1, D2);
            float2 v0 = upk(mel0), v1 = upk(mel1);
            float o00 = (__logf(fmaxf(v0.x, 0.0f) + 1e-5f) + 4.5f) * 0.2f;
            float o01 = (__logf(fmaxf(v0.y, 0.0f) + 1e-5f) + 4.5f) * 0.2f;
            float o10 = (__logf(fmaxf(v1.x, 0.0f) + 1e-5f) + 4.5f) * 0.2f;
            float o11 = (__logf(fmaxf(v1.y, 0.0f) + 1e-5f) + 4.5f) * 0.2f;
            float* o = out + ((size_t)(b * NMELS + m0)) * NFRAMES + t0;
            *reinterpret_cast<float2*>(o)           = make_float2(o00, o01);
            *reinterpret_cast<float2*>(o + NFRAMES) = make_float2(o10, o11);
        }
        // no trailing sync needed: next pass's stage-boundary barriers order
        // sz/spw reuse against this pass's reads
    }
}

extern "C" void kernel_launch(void* const* d_in, const int* in_sizes, int n_in,
                              void* d_out, int out_size) {
    const float* x = (const float*)d_in[0];
    // d_in[1] = fourier_basis, d_in[2] = mel_basis: both reproduced analytically
    float* out = (float*)d_out;

    int batch = in_sizes[0] / BATCH_SAMPLES;   // 32

    setup_kernel<<<1, 256>>>();

    dim3 grid(NFRAMES / (2 * PASSES), batch);
    logmel_kernel<<<grid, 64>>>(x, out);
}

// round 16
// speedup vs baseline: 1.0033x; 1.0033x over previous
#include <cuda_runtime.h>
#include <math.h>

#define BATCH_SAMPLES 320000
#define NFRAMES 1000
#define HOP 320
#define N2 512
#define NMELS 128
#define PREEMPH 0.97f
#define PASSES 2          // frame pairs per block (4 frames)

typedef unsigned long long u64;

// ---- global tables (rebuilt every launch; deterministic) ----
__device__ float2 g_win2[400];   // hann window pairs, index p-56
__device__ float2 g_tw[257];     // exp(-i*pi*k/512)
__device__ float  g_u[512];      // per-bin up-slope weight
__device__ int    g_seg[132];    // segment starts

__global__ void setup_kernel() {
    __shared__ int s_m[512];
    int tid = threadIdx.x;  // 256
    float* gw = reinterpret_cast<float*>(g_win2);
    for (int n = tid; n < 800; n += 256)
        gw[n] = 0.5f - 0.5f * __cosf((2.0f * (float)M_PI / 799.0f) * (float)n);
    for (int k = tid; k < 257; k += 256) {
        float s, c;
        __sincosf(-((float)M_PI / 512.0f) * (float)k, &s, &c);
        g_tw[k] = make_float2(c, s);
    }
    float mel_high = 1127.0f * logf(1.0f + 16000.0f / 700.0f);
    float invd = 129.0f / mel_high;
    for (int f = tid; f < 512; f += 256) {
        float melf = 1127.0f * logf(1.0f + (float)f * (31.25f / 700.0f));
        float md = melf * invd;
        int m = (int)floorf(md);
        g_u[f] = md - (float)m;
        s_m[f] = m;
    }
    __syncthreads();
    for (int f = tid; f < 512; f += 256) {
        int m0 = s_m[f];
        int mp = (f == 0) ? -1 : s_m[f - 1];
        for (int m = mp + 1; m <= m0; ++m) g_seg[m] = f;
        if (f == 511) for (int m = m0 + 1; m <= 131; ++m) g_seg[m] = 512;
    }
}

// ---- packed f32x2 helpers ----
__device__ __forceinline__ u64 pk(float a, float b) {
    u64 r; asm("mov.b64 %0, {%1, %2};" : "=l"(r)
               : "r"(__float_as_uint(a)), "r"(__float_as_uint(b)));
    return r;
}
__device__ __forceinline__ float2 upk(u64 v) {
    unsigned lo, hi; asm("mov.b64 {%0, %1}, %2;" : "=r"(lo), "=r"(hi) : "l"(v));
    return make_float2(__uint_as_float(lo), __uint_as_float(hi));
}
__device__ __forceinline__ u64 fadd2(u64 a, u64 b) {
    u64 r; asm("add.rn.f32x2 %0, %1, %2;" : "=l"(r) : "l"(a), "l"(b)); return r;
}
__device__ __forceinline__ u64 fsub2(u64 a, u64 b) {
    u64 r; asm("sub.rn.f32x2 %0, %1, %2;" : "=l"(r) : "l"(a), "l"(b)); return r;
}
__device__ __forceinline__ u64 fmul2(u64 a, u64 b) {
    u64 r; asm("mul.rn.f32x2 %0, %1, %2;" : "=l"(r) : "l"(a), "l"(b)); return r;
}
__device__ __forceinline__ u64 ffma2(u64 a, u64 b, u64 c) {
    u64 r; asm("fma.rn.f32x2 %0, %1, %2, %3;" : "=l"(r) : "l"(a), "l"(b), "l"(c)); return r;
}

// skewed addressing over 16B slots: conflict-free for strides 1, 8, 64 and dr_oct
__device__ __forceinline__ int PHYS(int i) { return i + (i >> 3) + (i >> 6); }
// octal digit reversal of a 9-bit index
__device__ __forceinline__ int dr_oct(int k) {
    return ((k & 7) << 6) | (k & 56) | ((k >> 6) & 7);
}

// 8-point DFT on packed pairs; no negations (add/sub folded)
__device__ __forceinline__ void dft8_2(u64* r, u64* i) {
    const u64 S22 = pk(0.70710678118654752f, 0.70710678118654752f);
    u64 br0 = fadd2(r[0], r[4]), bi0 = fadd2(i[0], i[4]);
    u64 br4 = fsub2(r[0], r[4]), bi4 = fsub2(i[0], i[4]);
    u64 t1r = fsub2(r[1], r[5]), t1i = fsub2(i[1], i[5]);
    u64 br1 = fadd2(r[1], r[5]), bi1 = fadd2(i[1], i[5]);
    u64 t2r = fsub2(r[2], r[6]), t2i = fsub2(i[2], i[6]);
    u64 br2 = fadd2(r[2], r[6]), bi2 = fadd2(i[2], i[6]);
    u64 t3r = fsub2(r[3], r[7]), t3i = fsub2(i[3], i[7]);
    u64 br3 = fadd2(r[3], r[7]), bi3 = fadd2(i[3], i[7]);
    u64 br5 = fmul2(S22, fadd2(t1r, t1i));
    u64 bi5 = fmul2(S22, fsub2(t1i, t1r));
    u64 p7r = fmul2(S22, fsub2(t3i, t3r));
    u64 p7e = fmul2(S22, fadd2(t3r, t3i));   // bi7 = -p7e
    u64 c0r = fadd2(br0, br2), c0i = fadd2(bi0, bi2);
    u64 c2r = fsub2(br0, br2), c2i = fsub2(bi0, bi2);
    u64 c1r = fadd2(br1, br3), c1i = fadd2(bi1, bi3);
    u64 d1r = fsub2(br1, br3), d1i = fsub2(bi1, bi3);
    u64 c4r = fadd2(br4, t2i), c4i = fsub2(bi4, t2r);
    u64 c6r = fsub2(br4, t2i), c6i = fadd2(bi4, t2r);
    u64 c5r = fadd2(br5, p7r), c5i = fsub2(bi5, p7e);
    u64 d3r = fsub2(br5, p7r), d3i = fadd2(bi5, p7e);
    r[0] = fadd2(c0r, c1r);  i[0] = fadd2(c0i, c1i);
    r[4] = fsub2(c0r, c1r);  i[4] = fsub2(c0i, c1i);
    r[2] = fadd2(c2r, d1i);  i[2] = fsub2(c2i, d1r);
    r[6] = fsub2(c2r, d1i);  i[6] = fadd2(c2i, d1r);
    r[1] = fadd2(c4r, c5r);  i[1] = fadd2(c4i, c5i);
    r[5] = fsub2(c4r, c5r);  i[5] = fsub2(c4i, c5i);
    r[3] = fadd2(c6r, d3i);  i[3] = fsub2(c6i, d3r);
    r[7] = fsub2(c6r, d3i);  i[7] = fadd2(c6i, d3r);
}

// twiddle via w2-stepped chains (dep depth <=4, low live regs)
__device__ __forceinline__ void twiddle8_2(u64* ar, u64* ai, u64 cw, u64 sw) {
    u64 c2 = fsub2(fmul2(cw, cw), fmul2(sw, sw));
    u64 s2 = fadd2(fmul2(cw, sw), fmul2(sw, cw));
    u64 cwr = cw, cwi = sw;     // odd cursor
    u64 evr = c2, evi = s2;     // even cursor
    #pragma unroll
    for (int k = 1; k < 8; k += 2) {
        u64 tr = fsub2(fmul2(ar[k], cwr), fmul2(ai[k], cwi));
        ai[k]  = ffma2(ar[k], cwi, fmul2(ai[k], cwr));
        ar[k]  = tr;
        if (k + 1 < 8) {
            u64 ur = fsub2(fmul2(ar[k+1], evr), fmul2(ai[k+1], evi));
            ai[k+1] = ffma2(ar[k+1], evi, fmul2(ai[k+1], evr));
            ar[k+1] = ur;
        }
        u64 nr = fsub2(fmul2(cwr, c2), fmul2(cwi, s2));
        cwi    = ffma2(cwr, s2, fmul2(cwi, c2));
        cwr    = nr;
        u64 mr = fsub2(fmul2(evr, c2), fmul2(evi, s2));
        evi    = ffma2(evr, s2, fmul2(evi, c2));
        evr    = mr;
    }
}

__device__ __forceinline__ float yval(const float* __restrict__ xb, int i) {
    return (i >= 0 && i <= BATCH_SAMPLES - 2) ? (xb[i + 1] - PREEMPH * xb[i]) : 0.0f;
}

// load + preemph + window for frame pair (t0, t0+1) into packed registers
__device__ __forceinline__ void load_input(
    const float* __restrict__ xb, int t0, int lane, u64* ar, u64* ai)
{
    const int basea = t0 * HOP - 512;
    if (t0 >= 2 && t0 + 1 <= 998) {
        #pragma unroll
        for (int m = 0; m < 8; ++m) {
            int p = lane + (m << 6);
            if (p >= 56 && p < 456) {
                int iaa = basea + 2 * p;
                float2 va = *reinterpret_cast<const float2*>(xb + iaa);
                float xa2 = xb[iaa + 2];
                float2 vb = *reinterpret_cast<const float2*>(xb + iaa + HOP);
                float xb2 = xb[iaa + HOP + 2];
                float2 w = __ldg(&g_win2[p - 56]);
                ar[m] = pk(w.x * (va.y - PREEMPH * va.x),
                           w.x * (vb.y - PREEMPH * vb.x));
                ai[m] = pk(w.y * (xa2 - PREEMPH * va.y),
                           w.y * (xb2 - PREEMPH * vb.y));
            } else { ar[m] = 0ULL; ai[m] = 0ULL; }
        }
    } else {
        #pragma unroll
        for (int m = 0; m < 8; ++m) {
            int p = lane + (m << 6);
            float a0 = 0.0f, a1 = 0.0f, b0 = 0.0f, b1 = 0.0f;
            if (p >= 56 && p < 456) {
                float2 w = __ldg(&g_win2[p - 56]);
                a0 = w.x * yval(xb, basea + 2 * p);
                a1 = w.y * yval(xb, basea + 2 * p + 1);
                b0 = w.x * yval(xb, basea + HOP + 2 * p);
                b1 = w.y * yval(xb, basea + HOP + 2 * p + 1);
            }
            ar[m] = pk(a0, b0); ai[m] = pk(a1, b1);
        }
    }
}

// 64 threads; block handles PASSES frame pairs with cross-pass input pipelining
__global__ __launch_bounds__(64, 10) void logmel_kernel(
    const float* __restrict__ x,
    float* __restrict__ out)
{
    __shared__ ulonglong2 sz[592];    // (re2, im2) FFT workspace, PHYS-skewed
    __shared__ u64        spw[513];   // packed power per bin
    __shared__ float      s_u[512];

    const int lane = threadIdx.x;     // 0..63
    const int b    = blockIdx.y;
    const float* __restrict__ xb = x + (size_t)b * BATCH_SAMPLES;

    // stage u table once (ordered by the stage-1/2 syncs before first use)
    #pragma unroll
    for (int c = 0; c < 8; ++c) s_u[lane + (c << 6)] = g_u[lane + (c << 6)];

    // pass-invariant mel segment boundaries
    const int m0 = 2 * lane;
    const int fa = __ldg(&g_seg[m0]);
    const int fb = __ldg(&g_seg[m0 + 1]);
    const int fc = __ldg(&g_seg[m0 + 2]);
    const int fd = __ldg(&g_seg[m0 + 3]);

    u64 ar[8], ai[8];
    load_input(xb, blockIdx.x * PASSES * 2, lane, ar, ai);

    #pragma unroll 1
    for (int pass = 0; pass < PASSES; ++pass) {
        const int t0 = (blockIdx.x * PASSES + pass) * 2;   // frames t0, t0+1

        // ---- stage 1: span 64 (input already in ar/ai) ----
        dft8_2(ar, ai);
        {
            float2 w = __ldg(&g_tw[2 * lane]);
            twiddle8_2(ar, ai, pk(w.x, w.x), pk(w.y, w.y));
        }
        #pragma unroll
        for (int k = 0; k < 8; ++k)
            sz[PHYS(lane + (k << 6))] = make_ulonglong2(ar[k], ai[k]);
        __syncthreads();

        // ---- stage 2: span 8 ----
        {
            const int G = lane >> 3, p = lane & 7;
            const int b0 = (G << 6) + p;
            #pragma unroll
            for (int m = 0; m < 8; ++m) {
                ulonglong2 v = sz[PHYS(b0 + (m << 3))];
                ar[m] = v.x; ai[m] = v.y;
            }
            dft8_2(ar, ai);
            float2 w = __ldg(&g_tw[p << 4]);
            twiddle8_2(ar, ai, pk(w.x, w.x), pk(w.y, w.y));
            #pragma unroll
            for (int k = 0; k < 8; ++k)
                sz[PHYS(b0 + (k << 3))] = make_ulonglong2(ar[k], ai[k]);
        }
        __syncthreads();

        // ---- stage 3: span 1; IN PLACE on thread-owned slots ----
        {
            const int b0 = lane << 3;
            #pragma unroll
            for (int m = 0; m < 8; ++m) {
                ulonglong2 v = sz[PHYS(b0 + m)];
                ar[m] = v.x; ai[m] = v.y;
            }
            dft8_2(ar, ai);
            #pragma unroll
            for (int k = 0; k < 8; ++k)
                sz[PHYS(b0 + k)] = make_ulonglong2(ar[k], ai[k]);
        }
        __syncthreads();

        // ---- PREFETCH next pass's input (LDG latency hidden by split+mel) ----
        u64 nar[8], nai[8];
        if (pass + 1 < PASSES)
            load_input(xb, (blockIdx.x * PASSES + pass + 1) * 2, lane, nar, nai);

        // ---- real-FFT split + power; gather via dr_oct ----
        const u64 HALF = pk(0.5f, 0.5f);
        #pragma unroll
        for (int kq = 0; kq < 4; ++kq) {
            int k  = lane + (kq << 6);            // 0..255
            int k2 = (N2 - k) & (N2 - 1);
            ulonglong2 z = sz[PHYS(dr_oct(k))];
            ulonglong2 u = sz[PHYS(dr_oct(k2))];
            u64 xer  = fmul2(HALF, fadd2(z.x, u.x));
            u64 xei  = fmul2(HALF, fsub2(z.y, u.y));
            u64 xodr = fmul2(HALF, fadd2(z.y, u.y));
            u64 xodi = fmul2(HALF, fsub2(u.x, z.x));
            float2 w = __ldg(&g_tw[k]);
            u64 WC = pk(w.x, w.x), WS = pk(w.y, w.y);
            u64 tr = fsub2(fmul2(WC, xodr), fmul2(WS, xodi));
            u64 ti = ffma2(WC, xodi, fmul2(WS, xodr));
            u64 xr = fadd2(xer, tr), xi = fadd2(xei, ti);
            u64 yr = fsub2(xer, tr), yi = fsub2(xei, ti);
            spw[k]      = ffma2(xr, xr, fmul2(xi, xi));
            spw[N2 - k] = ffma2(yr, yr, fmul2(yi, yi));
        }
        if (lane == 0) {
            ulonglong2 z = sz[PHYS(dr_oct(256))];
            spw[256] = ffma2(z.x, z.x, fmul2(z.y, z.y));
        }
        __syncthreads();

        // ---- mel: thread owns mels (2*lane, 2*lane+1); each bin read once ----
        {
            u64 P0 = 0ULL, U0 = 0ULL, P1 = 0ULL, U1 = 0ULL;
            for (int f = fa; f < fb; ++f) {
                u64 p = spw[f]; float uf = s_u[f];
                P0 = fadd2(P0, p); U0 = ffma2(pk(uf, uf), p, U0);
            }
            for (int f = fb; f < fc; ++f) {
                u64 p = spw[f]; float uf = s_u[f];
                P1 = fadd2(P1, p); U1 = ffma2(pk(uf, uf), p, U1);
            }
            u64 D0 = fsub2(P0, U0);
            u64 D2 = __shfl_down_sync(0xffffffffu, D0, 1);
            if ((lane & 31) == 31) {                      // warp boundary: recompute
                u64 P2 = 0ULL, U2 = 0ULL;
                for (int f = fc; f < fd; ++f) {
                    u64 p = spw[f]; float uf = s_u[f];
                    P2 = fadd2(P2, p); U2 = ffma2(pk(uf, uf), p, U2);
                }
                D2 = fsub2(P2, U2);
            }
            u64 mel0 = fadd2(U0, fsub2(P1, U1));
            u64 mel1 = fadd2(U1, D2);
            float2 v0 = upk(mel0), v1 = upk(mel1);
            float o00 = (__logf(fmaxf(v0.x, 0.0f) + 1e-5f) + 4.5f) * 0.2f;
            float o01 = (__logf(fmaxf(v0.y, 0.0f) + 1e-5f) + 4.5f) * 0.2f;
            float o10 = (__logf(fmaxf(v1.x, 0.0f) + 1e-5f) + 4.5f) * 0.2f;
            float o11 = (__logf(fmaxf(v1.y, 0.0f) + 1e-5f) + 4.5f) * 0.2f;
            float* o = out + ((size_t)(b * NMELS + m0)) * NFRAMES + t0;
            *reinterpret_cast<float2*>(o)           = make_float2(o00, o01);
            *reinterpret_cast<float2*>(o + NFRAMES) = make_float2(o10, o11);
        }

        // rotate prefetched input into place for the next pass
        if (pass + 1 < PASSES) {
            #pragma unroll
            for (int m = 0; m < 8; ++m) { ar[m] = nar[m]; ai[m] = nai[m]; }
        }
        // no trailing sync needed: next pass's stage-boundary barriers order
        // sz/spw reuse against this pass's reads
    }
}

extern "C" void kernel_launch(void* const* d_in, const int* in_sizes, int n_in,
                              void* d_out, int out_size) {
    const float* x = (const float*)d_in[0];
    // d_in[1] = fourier_basis, d_in[2] = mel_basis: both reproduced analytically
    float* out = (float*)d_out;

    int batch = in_sizes[0] / BATCH_SAMPLES;   // 32

    setup_kernel<<<1, 256>>>();

    dim3 grid(NFRAMES / (2 * PASSES), batch);
    logmel_kernel<<<grid, 64>>>(x, out);
}

// round 17
// speedup vs baseline: 1.0309x; 1.0275x over previous
#include <cuda_runtime.h>
#include <math.h>

#define BATCH_SAMPLES 320000
#define NFRAMES 1000
#define HOP 320
#define N2 512
#define NMELS 128
#define PREEMPH 0.97f
#define PASSES 2          // frame pairs per block (4 frames)

typedef unsigned long long u64;

// ---- global tables (rebuilt every launch; deterministic) ----
__device__ float2 g_win2[400];   // hann window pairs, index p-56
__device__ float2 g_tw[257];     // exp(-i*pi*k/512)
__device__ float  g_u[512];      // per-bin up-slope weight
__device__ int    g_seg[132];    // segment starts

// 512 threads, no shared, no syncs
__global__ void setup_kernel() {
    int tid = threadIdx.x;  // 0..511
    float* gw = reinterpret_cast<float*>(g_win2);
    // window: 800 values
    for (int n = tid; n < 800; n += 512)
        gw[n] = 0.5f - 0.5f * __cosf((2.0f * (float)M_PI / 799.0f) * (float)n);
    // twiddles: 257 values
    if (tid < 257) {
        float s, c;
        __sincosf(-((float)M_PI / 512.0f) * (float)tid, &s, &c);
        g_tw[tid] = make_float2(c, s);
    }
    // mel scale: delta = mel(16000)/129 ; m(f)=floor(mel_f/delta), u=frac
    const float mel_high = 1127.0f * logf(1.0f + 16000.0f / 700.0f);
    const float invd = 129.0f / mel_high;
    {
        int f = tid;  // 0..511, exactly one per thread
        float melf = 1127.0f * logf(1.0f + (float)f * (31.25f / 700.0f));
        float md = melf * invd;
        int m0 = (int)floorf(md);
        g_u[f] = md - (float)m0;
        // segment starts: recompute m(f-1) directly (no shared round-trip)
        int mp;
        if (f == 0) mp = -1;
        else {
            float melp = 1127.0f * logf(1.0f + (float)(f - 1) * (31.25f / 700.0f));
            mp = (int)floorf(melp * invd);
        }
        for (int m = mp + 1; m <= m0; ++m) g_seg[m] = f;
        if (f == 511)
            for (int m = m0 + 1; m <= 131; ++m) g_seg[m] = 512;
    }
}

// ---- packed f32x2 helpers ----
__device__ __forceinline__ u64 pk(float a, float b) {
    u64 r; asm("mov.b64 %0, {%1, %2};" : "=l"(r)
               : "r"(__float_as_uint(a)), "r"(__float_as_uint(b)));
    return r;
}
__device__ __forceinline__ float2 upk(u64 v) {
    unsigned lo, hi; asm("mov.b64 {%0, %1}, %2;" : "=r"(lo), "=r"(hi) : "l"(v));
    return make_float2(__uint_as_float(lo), __uint_as_float(hi));
}
__device__ __forceinline__ u64 fadd2(u64 a, u64 b) {
    u64 r; asm("add.rn.f32x2 %0, %1, %2;" : "=l"(r) : "l"(a), "l"(b)); return r;
}
__device__ __forceinline__ u64 fsub2(u64 a, u64 b) {
    u64 r; asm("sub.rn.f32x2 %0, %1, %2;" : "=l"(r) : "l"(a), "l"(b)); return r;
}
__device__ __forceinline__ u64 fmul2(u64 a, u64 b) {
    u64 r; asm("mul.rn.f32x2 %0, %1, %2;" : "=l"(r) : "l"(a), "l"(b)); return r;
}
__device__ __forceinline__ u64 ffma2(u64 a, u64 b, u64 c) {
    u64 r; asm("fma.rn.f32x2 %0, %1, %2, %3;" : "=l"(r) : "l"(a), "l"(b), "l"(c)); return r;
}

// skewed addressing over 16B slots: conflict-free for strides 1, 8, 64 and dr_oct
__device__ __forceinline__ int PHYS(int i) { return i + (i >> 3) + (i >> 6); }
// octal digit reversal of a 9-bit index
__device__ __forceinline__ int dr_oct(int k) {
    return ((k & 7) << 6) | (k & 56) | ((k >> 6) & 7);
}

// 8-point DFT on packed pairs; no negations (add/sub folded)
__device__ __forceinline__ void dft8_2(u64* r, u64* i) {
    const u64 S22 = pk(0.70710678118654752f, 0.70710678118654752f);
    u64 br0 = fadd2(r[0], r[4]), bi0 = fadd2(i[0], i[4]);
    u64 br4 = fsub2(r[0], r[4]), bi4 = fsub2(i[0], i[4]);
    u64 t1r = fsub2(r[1], r[5]), t1i = fsub2(i[1], i[5]);
    u64 br1 = fadd2(r[1], r[5]), bi1 = fadd2(i[1], i[5]);
    u64 t2r = fsub2(r[2], r[6]), t2i = fsub2(i[2], i[6]);
    u64 br2 = fadd2(r[2], r[6]), bi2 = fadd2(i[2], i[6]);
    u64 t3r = fsub2(r[3], r[7]), t3i = fsub2(i[3], i[7]);
    u64 br3 = fadd2(r[3], r[7]), bi3 = fadd2(i[3], i[7]);
    u64 br5 = fmul2(S22, fadd2(t1r, t1i));
    u64 bi5 = fmul2(S22, fsub2(t1i, t1r));
    u64 p7r = fmul2(S22, fsub2(t3i, t3r));
    u64 p7e = fmul2(S22, fadd2(t3r, t3i));   // bi7 = -p7e
    u64 c0r = fadd2(br0, br2), c0i = fadd2(bi0, bi2);
    u64 c2r = fsub2(br0, br2), c2i = fsub2(bi0, bi2);
    u64 c1r = fadd2(br1, br3), c1i = fadd2(bi1, bi3);
    u64 d1r = fsub2(br1, br3), d1i = fsub2(bi1, bi3);
    u64 c4r = fadd2(br4, t2i), c4i = fsub2(bi4, t2r);
    u64 c6r = fsub2(br4, t2i), c6i = fadd2(bi4, t2r);
    u64 c5r = fadd2(br5, p7r), c5i = fsub2(bi5, p7e);
    u64 d3r = fsub2(br5, p7r), d3i = fadd2(bi5, p7e);
    r[0] = fadd2(c0r, c1r);  i[0] = fadd2(c0i, c1i);
    r[4] = fsub2(c0r, c1r);  i[4] = fsub2(c0i, c1i);
    r[2] = fadd2(c2r, d1i);  i[2] = fsub2(c2i, d1r);
    r[6] = fsub2(c2r, d1i);  i[6] = fadd2(c2i, d1r);
    r[1] = fadd2(c4r, c5r);  i[1] = fadd2(c4i, c5i);
    r[5] = fsub2(c4r, c5r);  i[5] = fsub2(c4i, c5i);
    r[3] = fadd2(c6r, d3i);  i[3] = fsub2(c6i, d3r);
    r[7] = fsub2(c6r, d3i);  i[7] = fadd2(c6i, d3r);
}

// twiddle via w2-stepped chains (dep depth <=4, low live regs)
__device__ __forceinline__ void twiddle8_2(u64* ar, u64* ai, u64 cw, u64 sw) {
    u64 c2 = fsub2(fmul2(cw, cw), fmul2(sw, sw));
    u64 s2 = fadd2(fmul2(cw, sw), fmul2(sw, cw));
    u64 cwr = cw, cwi = sw;     // odd cursor
    u64 evr = c2, evi = s2;     // even cursor
    #pragma unroll
    for (int k = 1; k < 8; k += 2) {
        u64 tr = fsub2(fmul2(ar[k], cwr), fmul2(ai[k], cwi));
        ai[k]  = ffma2(ar[k], cwi, fmul2(ai[k], cwr));
        ar[k]  = tr;
        if (k + 1 < 8) {
            u64 ur = fsub2(fmul2(ar[k+1], evr), fmul2(ai[k+1], evi));
            ai[k+1] = ffma2(ar[k+1], evi, fmul2(ai[k+1], evr));
            ar[k+1] = ur;
        }
        u64 nr = fsub2(fmul2(cwr, c2), fmul2(cwi, s2));
        cwi    = ffma2(cwr, s2, fmul2(cwi, c2));
        cwr    = nr;
        u64 mr = fsub2(fmul2(evr, c2), fmul2(evi, s2));
        evi    = ffma2(evr, s2, fmul2(evi, c2));
        evr    = mr;
    }
}

__device__ __forceinline__ float yval(const float* __restrict__ xb, int i) {
    return (i >= 0 && i <= BATCH_SAMPLES - 2) ? (xb[i + 1] - PREEMPH * xb[i]) : 0.0f;
}

// 64 threads; block handles PASSES frame pairs sequentially
__global__ __launch_bounds__(64, 15) void logmel_kernel(
    const float* __restrict__ x,
    float* __restrict__ out)
{
    __shared__ ulonglong2 sz[592];    // (re2, im2) FFT workspace, PHYS-skewed
    __shared__ u64        spw[513];   // packed power per bin
    __shared__ float      s_u[512];

    const int lane = threadIdx.x;     // 0..63
    const int b    = blockIdx.y;
    const float* __restrict__ xb = x + (size_t)b * BATCH_SAMPLES;

    // stage u table once (ordered by the stage-1/2 syncs before first use)
    #pragma unroll
    for (int c = 0; c < 8; ++c) s_u[lane + (c << 6)] = g_u[lane + (c << 6)];

    // pass-invariant mel segment boundaries
    const int m0 = 2 * lane;
    const int fa = __ldg(&g_seg[m0]);
    const int fb = __ldg(&g_seg[m0 + 1]);
    const int fc = __ldg(&g_seg[m0 + 2]);
    const int fd = __ldg(&g_seg[m0 + 3]);

    #pragma unroll 1
    for (int pass = 0; pass < PASSES; ++pass) {
        const int t0 = (blockIdx.x * PASSES + pass) * 2;   // frames t0, t0+1
        const int basea = t0 * HOP - 512;
        u64 ar[8], ai[8];

        // ---- load + preemph + window -> packed stage-1 registers ----
        if (t0 >= 2 && t0 + 1 <= 998) {
            #pragma unroll
            for (int m = 0; m < 8; ++m) {
                int p = lane + (m << 6);
                if (p >= 56 && p < 456) {
                    int iaa = basea + 2 * p;
                    float2 va = *reinterpret_cast<const float2*>(xb + iaa);
                    float xa2 = xb[iaa + 2];
                    float2 vb = *reinterpret_cast<const float2*>(xb + iaa + HOP);
                    float xb2 = xb[iaa + HOP + 2];
                    float2 w = __ldg(&g_win2[p - 56]);
                    ar[m] = pk(w.x * (va.y - PREEMPH * va.x),
                               w.x * (vb.y - PREEMPH * vb.x));
                    ai[m] = pk(w.y * (xa2 - PREEMPH * va.y),
                               w.y * (xb2 - PREEMPH * vb.y));
                } else { ar[m] = 0ULL; ai[m] = 0ULL; }
            }
        } else {
            #pragma unroll
            for (int m = 0; m < 8; ++m) {
                int p = lane + (m << 6);
                float a0 = 0.0f, a1 = 0.0f, b0 = 0.0f, b1 = 0.0f;
                if (p >= 56 && p < 456) {
                    float2 w = __ldg(&g_win2[p - 56]);
                    a0 = w.x * yval(xb, basea + 2 * p);
                    a1 = w.y * yval(xb, basea + 2 * p + 1);
                    b0 = w.x * yval(xb, basea + HOP + 2 * p);
                    b1 = w.y * yval(xb, basea + HOP + 2 * p + 1);
                }
                ar[m] = pk(a0, b0); ai[m] = pk(a1, b1);
            }
        }

        // ---- stage 1: span 64 ----
        dft8_2(ar, ai);
        {
            float2 w = __ldg(&g_tw[2 * lane]);
            twiddle8_2(ar, ai, pk(w.x, w.x), pk(w.y, w.y));
        }
        #pragma unroll
        for (int k = 0; k < 8; ++k)
            sz[PHYS(lane + (k << 6))] = make_ulonglong2(ar[k], ai[k]);
        __syncthreads();

        // ---- stage 2: span 8 ----
        {
            const int G = lane >> 3, p = lane & 7;
            const int b0 = (G << 6) + p;
            #pragma unroll
            for (int m = 0; m < 8; ++m) {
                ulonglong2 v = sz[PHYS(b0 + (m << 3))];
                ar[m] = v.x; ai[m] = v.y;
            }
            dft8_2(ar, ai);
            float2 w = __ldg(&g_tw[p << 4]);
            twiddle8_2(ar, ai, pk(w.x, w.x), pk(w.y, w.y));
            #pragma unroll
            for (int k = 0; k < 8; ++k)
                sz[PHYS(b0 + (k << 3))] = make_ulonglong2(ar[k], ai[k]);
        }
        __syncthreads();

        // ---- stage 3: span 1; IN PLACE on thread-owned slots ----
        {
            const int b0 = lane << 3;
            #pragma unroll
            for (int m = 0; m < 8; ++m) {
                ulonglong2 v = sz[PHYS(b0 + m)];
                ar[m] = v.x; ai[m] = v.y;
            }
            dft8_2(ar, ai);
            #pragma unroll
            for (int k = 0; k < 8; ++k)
                sz[PHYS(b0 + k)] = make_ulonglong2(ar[k], ai[k]);
        }
        __syncthreads();

        // ---- real-FFT split + power; gather via dr_oct ----
        const u64 HALF = pk(0.5f, 0.5f);
        #pragma unroll
        for (int kq = 0; kq < 4; ++kq) {
            int k  = lane + (kq << 6);            // 0..255
            int k2 = (N2 - k) & (N2 - 1);
            ulonglong2 z = sz[PHYS(dr_oct(k))];
            ulonglong2 u = sz[PHYS(dr_oct(k2))];
            u64 xer  = fmul2(HALF, fadd2(z.x, u.x));
            u64 xei  = fmul2(HALF, fsub2(z.y, u.y));
            u64 xodr = fmul2(HALF, fadd2(z.y, u.y));
            u64 xodi = fmul2(HALF, fsub2(u.x, z.x));
            float2 w = __ldg(&g_tw[k]);
            u64 WC = pk(w.x, w.x), WS = pk(w.y, w.y);
            u64 tr = fsub2(fmul2(WC, xodr), fmul2(WS, xodi));
            u64 ti = ffma2(WC, xodi, fmul2(WS, xodr));
            u64 xr = fadd2(xer, tr), xi = fadd2(xei, ti);
            u64 yr = fsub2(xer, tr), yi = fsub2(xei, ti);
            spw[k]      = ffma2(xr, xr, fmul2(xi, xi));
            spw[N2 - k] = ffma2(yr, yr, fmul2(yi, yi));
        }
        if (lane == 0) {
            ulonglong2 z = sz[PHYS(dr_oct(256))];
            spw[256] = ffma2(z.x, z.x, fmul2(z.y, z.y));
        }
        __syncthreads();

        // ---- mel: thread owns mels (2*lane, 2*lane+1); each bin read once ----
        {
            u64 P0 = 0ULL, U0 = 0ULL, P1 = 0ULL, U1 = 0ULL;
            for (int f = fa; f < fb; ++f) {
                u64 p = spw[f]; float uf = s_u[f];
                P0 = fadd2(P0, p); U0 = ffma2(pk(uf, uf), p, U0);
            }
            for (int f = fb; f < fc; ++f) {
                u64 p = spw[f]; float uf = s_u[f];
                P1 = fadd2(P1, p); U1 = ffma2(pk(uf, uf), p, U1);
            }
            u64 D0 = fsub2(P0, U0);
            u64 D2 = __shfl_down_sync(0xffffffffu, D0, 1);
            if ((lane & 31) == 31) {                      // warp boundary: recompute
                u64 P2 = 0ULL, U2 = 0ULL;
                for (int f = fc; f < fd; ++f) {
                    u64 p = spw[f]; float uf = s_u[f];
                    P2 = fadd2(P2, p); U2 = ffma2(pk(uf, uf), p, U2);
                }
                D2 = fsub2(P2, U2);
            }
            u64 mel0 = fadd2(U0, fsub2(P1, U1));
            u64 mel1 = fadd2(U1, D2);
            float2 v0 = upk(mel0), v1 = upk(mel1);
            float o00 = (__logf(fmaxf(v0.x, 0.0f) + 1e-5f) + 4.5f) * 0.2f;
            float o01 = (__logf(fmaxf(v0.y, 0.0f) + 1e-5f) + 4.5f) * 0.2f;
            float o10 = (__logf(fmaxf(v1.x, 0.0f) + 1e-5f) + 4.5f) * 0.2f;
            float o11 = (__logf(fmaxf(v1.y, 0.0f) + 1e-5f) + 4.5f) * 0.2f;
            float* o = out + ((size_t)(b * NMELS + m0)) * NFRAMES + t0;
            *reinterpret_cast<float2*>(o)           = make_float2(o00, o01);
            *reinterpret_cast<float2*>(o + NFRAMES) = make_float2(o10, o11);
        }
        // no trailing sync needed: next pass's stage-boundary barriers order
        // sz/spw reuse against this pass's reads
    }
}

extern "C" void kernel_launch(void* const* d_in, const int* in_sizes, int n_in,
                              void* d_out, int out_size) {
    const float* x = (const float*)d_in[0];
    // d_in[1] = fourier_basis, d_in[2] = mel_basis: both reproduced analytically
    float* out = (float*)d_out;

    int batch = in_sizes[0] / BATCH_SAMPLES;   // 32

    setup_kernel<<<1, 512>>>();

    dim3 grid(NFRAMES / (2 * PASSES), batch);
    logmel_kernel<<<grid, 64>>>(x, out);
}